// round 7
// baseline (speedup 1.0000x reference)
#include <cuda_runtime.h>
#include <math.h>

// Problem constants
#define BN     256
#define HN     128
#define CN     32
#define OUTN   32
#define NSTAGE 256   // 64 steps * 4 RK stages
#define GRID   128
#define NTHR   512

// ---------------- device global scratch (allocation-free) ----------------
__device__ float g_k[4][BN * HN];      // k1..k4 of current step
__device__ float g_Bv[BN * HN];        // h2 for current stage
__device__ float g_dX[BN * CN];        // dX/dt at current stage time
__device__ int   g_flags[2 * GRID];    // [0..127]=p1done, [128..255]=p2done (stage+1)

struct SmemLayout {
    float W3s[128][256];     // 128 KB : this CTA's 8-h slice of W3 [i][wl*32+c]
    float W1s[128][128];     // 64 KB
    float BvT[128][36];      // transposed h2 tile [i][b], padded for LDS128
    float dXs[32][36];
    float ys[2][128];
    float As[2][128];
    float z0s[2][128];
    float b1s[128];
    float b2s[128];
};

__device__ __forceinline__ float softplus_f(float x) {
    return fmaxf(x, 0.0f) + __logf(1.0f + __expf(-fabsf(x)));
}
__device__ __forceinline__ float tanh_fast(float x) {
    float e = __expf(2.0f * x);
    return 1.0f - __fdividef(2.0f, e + 1.0f);
}
__device__ __forceinline__ unsigned long long pk2(float lo, float hi) {
    unsigned long long r;
    asm("mov.b64 %0, {%1,%2};" : "=l"(r) : "f"(lo), "f"(hi));
    return r;
}
__device__ __forceinline__ void unpk2(unsigned long long v, float& lo, float& hi) {
    asm("mov.b64 {%0,%1}, %2;" : "=f"(lo), "=f"(hi) : "l"(v));
}
__device__ __forceinline__ void ffma2(unsigned long long& d, unsigned long long a,
                                      unsigned long long b) {
    asm("fma.rn.f32x2 %0, %1, %2, %0;" : "+l"(d) : "l"(a), "l"(b));
}

__device__ __forceinline__ void spin_ge(volatile int* f, int tgt) {
    while (*f < tgt) { }
}
__device__ __forceinline__ void publish(int idx, int val) {
    __threadfence();
    *(volatile int*)&g_flags[idx] = val;
}

__global__ __launch_bounds__(NTHR, 1) void cde_kernel(
    const float* __restrict__ coeffs, const float* __restrict__ x_last,
    const float* __restrict__ Wi,     const float* __restrict__ bi,
    const float* __restrict__ W1,     const float* __restrict__ b1,
    const float* __restrict__ W2,     const float* __restrict__ b2,
    const float* __restrict__ W3,     const float* __restrict__ b3,
    const float* __restrict__ Wr,     const float* __restrict__ br,
    float* __restrict__ out)
{
    extern __shared__ char smraw[];
    SmemLayout& sm = *reinterpret_cast<SmemLayout*>(smraw);

    const int tid = threadIdx.x;
    const int ci  = blockIdx.x;
    const int hg  = ci & 15;          // h-group: h in [hg*8, hg*8+8)
    const int bB  = (ci >> 4) * 32;   // phase-2 b-tile base
    const int grp = (ci >> 4) * 16;   // base CTA of this independent 16-CTA group

    // ---- one-time smem loads ----
    for (int t = tid; t < 128 * 256; t += NTHR) {
        int i = t >> 8, cc = t & 255;
        sm.W3s[i][cc] = W3[i * 4096 + hg * 256 + cc];
    }
    for (int t = tid; t < 128 * 128; t += NTHR)
        sm.W1s[t >> 7][t & 127] = W1[t];
    if (tid < 128) { sm.b1s[tid] = b1[tid]; sm.b2s[tid] = b2[tid]; }

    // ---- phase-2 mapping ----
    const int wid  = tid >> 5;
    const int lane = tid & 31;
    const int wl   = wid & 7;         // local h
    const int sub  = wid >> 3;        // b-half (0/1)
    const int cg   = lane & 7;        // c-group of 4
    const int bgr  = lane >> 3;       // b-group of 4
    const int c0   = cg * 4;
    const int b0l  = sub * 16 + bgr * 4;   // 4 b-rows per thread
    const int h    = hg * 8 + wl;

    float b3v[4];
    #pragma unroll
    for (int u = 0; u < 4; u++) b3v[u] = b3[h * 32 + c0 + u];

    // ---- phase-1 y/dX mapping (first 256 threads) ----
    const int bb256 = (tid >> 7) & 1;
    const int j256  = tid & 127;
    const int bme256 = ci * 2 + bb256;

    // ---- phase-1 matvec mapping (all 512 threads, intra-warp i-split) ----
    const int mbb   = wid >> 3;            // batch row (0/1)
    const int mj    = (wid & 7) * 16 + (lane & 15);
    const int mi0   = (lane >> 4) * 64;    // i-half
    const int mwrite = (lane < 16);

    __syncthreads();

    for (int s = 0; s < NSTAGE; s++) {
        const int s4 = s & 3;
        const int n  = s >> 2;

        // ---- wait: previous stage's k (and Bv/dX buffer release) from our group ----
        if (s > 0) {
            if (tid < 16) spin_ge((volatile int*)&g_flags[GRID + grp + tid], s);
            __syncthreads();
        }

        // ============ phase 1 : y, dX, h1, h2  (2 batch rows / CTA) ============
        if (tid < 256) {
            float y;
            if (s == 0) {
                float acc = bi[j256];
                const float* cb = coeffs + bme256 * 8192;
                #pragma unroll
                for (int c = 0; c < CN; c++) acc = fmaf(cb[c], Wi[c * 128 + j256], acc);
                sm.z0s[bb256][j256] = acc;
                y = acc;
            } else {
                float z0 = sm.z0s[bb256][j256];
                if (s4 == 0) {
                    float k1 = __ldcg(&g_k[0][bme256 * 128 + j256]);
                    float k2 = __ldcg(&g_k[1][bme256 * 128 + j256]);
                    float k3 = __ldcg(&g_k[2][bme256 * 128 + j256]);
                    float k4 = __ldcg(&g_k[3][bme256 * 128 + j256]);
                    z0 += (k1 + 3.0f * (k2 + k3) + k4) * 0.125f;
                    sm.z0s[bb256][j256] = z0;
                    y = z0;
                } else if (s4 == 1) {
                    y = z0 + __ldcg(&g_k[0][bme256 * 128 + j256]) * (1.0f / 3.0f);
                } else if (s4 == 2) {
                    y = z0 + __ldcg(&g_k[1][bme256 * 128 + j256])
                           - __ldcg(&g_k[0][bme256 * 128 + j256]) * (1.0f / 3.0f);
                } else {
                    y = z0 + __ldcg(&g_k[0][bme256 * 128 + j256])
                           - __ldcg(&g_k[1][bme256 * 128 + j256])
                           + __ldcg(&g_k[2][bme256 * 128 + j256]);
                }
            }
            sm.ys[bb256][j256] = y;

            if (j256 < CN) {
                float t;
                if      (s4 == 0) t = (float)n;
                else if (s4 == 1) t = (float)n + (1.0f / 3.0f);
                else if (s4 == 2) t = (float)n + (2.0f / 3.0f);
                else              t = (float)(n + 1);
                int   pid  = (int)floorf(t); if (pid > 63) pid = 63;
                float frac = t - (float)pid;
                const float* cb = coeffs + bme256 * 8192 + pid * 128;
                float dv = fmaf(fmaf(cb[96 + j256], frac, cb[64 + j256]), frac, cb[32 + j256]);
                __stcg(&g_dX[bme256 * 32 + j256], dv);
            }
        }
        __syncthreads();

        {   // matvec1 : intra-warp i-split, shfl combine
            float acc = 0.0f;
            #pragma unroll 8
            for (int i = 0; i < 64; i++)
                acc = fmaf(sm.ys[mbb][mi0 + i], sm.W1s[mi0 + i][mj], acc);
            acc += __shfl_xor_sync(0xffffffffu, acc, 16);
            if (mwrite)
                sm.As[mbb][mj] = softplus_f(acc + sm.b1s[mj]);
        }
        __syncthreads();
        {   // matvec2
            float acc = 0.0f;
            #pragma unroll 8
            for (int i = 0; i < 64; i++)
                acc = fmaf(sm.As[mbb][mi0 + i], __ldg(&W2[(mi0 + i) * 128 + mj]), acc);
            acc += __shfl_xor_sync(0xffffffffu, acc, 16);
            if (mwrite)
                __stcg(&g_Bv[(ci * 2 + mbb) * 128 + mj],
                       softplus_f(acc + sm.b2s[mj]));
        }
        __syncthreads();
        if (tid == 0) publish(ci, s + 1);          // p1done

        // ---- wait: all 16 producers of our b-tile ----
        if (tid < 16) spin_ge((volatile int*)&g_flags[grp + tid], s + 1);
        __syncthreads();

        // ============ phase 2 : k = tanh(h2 @ W3 + b3) . dX  (32b x 8h) ============
        {
            for (int t = tid; t < 32 * 128; t += NTHR) {
                int r = t >> 7, q = t & 127;
                sm.BvT[q][r] = __ldcg(&g_Bv[(bB + r) * 128 + q]);
            }
            for (int t = tid; t < 32 * 32; t += NTHR) {
                int r = t >> 5, q = t & 31;
                sm.dXs[r][q] = __ldcg(&g_dX[(bB + r) * 32 + q]);
            }
            __syncthreads();

            unsigned long long acc[2][4];
            #pragma unroll
            for (int p = 0; p < 2; p++)
                #pragma unroll
                for (int u = 0; u < 4; u++) acc[p][u] = 0ULL;

            #pragma unroll 4
            for (int i = 0; i < 128; i++) {
                float4 w4 = *reinterpret_cast<const float4*>(&sm.W3s[i][wl * 32 + c0]);
                ulonglong2 bv = *reinterpret_cast<const ulonglong2*>(&sm.BvT[i][b0l]);
                unsigned long long w0  = pk2(w4.x, w4.x);
                unsigned long long w1d = pk2(w4.y, w4.y);
                unsigned long long w2d = pk2(w4.z, w4.z);
                unsigned long long w3d = pk2(w4.w, w4.w);
                ffma2(acc[0][0], bv.x, w0);
                ffma2(acc[0][1], bv.x, w1d);
                ffma2(acc[0][2], bv.x, w2d);
                ffma2(acc[0][3], bv.x, w3d);
                ffma2(acc[1][0], bv.y, w0);
                ffma2(acc[1][1], bv.y, w1d);
                ffma2(acc[1][2], bv.y, w2d);
                ffma2(acc[1][3], bv.y, w3d);
            }

            float pj[4] = {0.0f, 0.0f, 0.0f, 0.0f};
            #pragma unroll
            for (int p = 0; p < 2; p++) {
                #pragma unroll
                for (int u = 0; u < 4; u++) {
                    float lo, hi;
                    unpk2(acc[p][u], lo, hi);
                    pj[2 * p]     = fmaf(tanh_fast(lo + b3v[u]),
                                         sm.dXs[b0l + 2 * p][c0 + u], pj[2 * p]);
                    pj[2 * p + 1] = fmaf(tanh_fast(hi + b3v[u]),
                                         sm.dXs[b0l + 2 * p + 1][c0 + u], pj[2 * p + 1]);
                }
            }
            #pragma unroll
            for (int m = 1; m < 8; m <<= 1)
                #pragma unroll
                for (int r = 0; r < 4; r++)
                    pj[r] += __shfl_xor_sync(0xffffffffu, pj[r], m);

            if (cg == 0) {
                #pragma unroll
                for (int r = 0; r < 4; r++)
                    __stcg(&g_k[s4][(bB + b0l + r) * 128 + h], pj[r]);
            }
        }
        __syncthreads();
        if (tid == 0) publish(GRID + ci, s + 1);   // p2done
    }

    // ================= epilogue: fold last step, readout =================
    if (tid < 16) spin_ge((volatile int*)&g_flags[GRID + grp + tid], NSTAGE);
    __syncthreads();

    if (tid < 256) {
        float z0 = sm.z0s[bb256][j256];
        float k1 = __ldcg(&g_k[0][bme256 * 128 + j256]);
        float k2 = __ldcg(&g_k[1][bme256 * 128 + j256]);
        float k3 = __ldcg(&g_k[2][bme256 * 128 + j256]);
        float k4 = __ldcg(&g_k[3][bme256 * 128 + j256]);
        sm.ys[bb256][j256] = z0 + (k1 + 3.0f * (k2 + k3) + k4) * 0.125f;
    }
    __syncthreads();
    if (tid < 256 && j256 < OUTN) {
        float acc = br[j256] + x_last[bme256 * OUTN + j256];
        #pragma unroll 8
        for (int hh = 0; hh < 128; hh++)
            acc = fmaf(sm.ys[bb256][hh], Wr[hh * OUTN + j256], acc);
        out[bme256 * OUTN + j256] = acc;
    }
}

extern "C" void kernel_launch(void* const* d_in, const int* in_sizes, int n_in,
                              void* d_out, int out_size) {
    const float* coeffs = (const float*)d_in[0];
    const float* x_last = (const float*)d_in[1];
    const float* Wi     = (const float*)d_in[2];
    const float* bi     = (const float*)d_in[3];
    const float* W1     = (const float*)d_in[4];
    const float* b1     = (const float*)d_in[5];
    const float* W2     = (const float*)d_in[6];
    const float* b2     = (const float*)d_in[7];
    const float* W3     = (const float*)d_in[8];
    const float* b3     = (const float*)d_in[9];
    const float* Wr     = (const float*)d_in[10];
    const float* br     = (const float*)d_in[11];
    float* out = (float*)d_out;

    static const size_t SMEM = sizeof(SmemLayout);
    cudaFuncSetAttribute(cde_kernel, cudaFuncAttributeMaxDynamicSharedMemorySize, (int)SMEM);

    // reset p2p flags (graph-capturable async memset)
    void* flagaddr = nullptr;
    cudaGetSymbolAddress(&flagaddr, g_flags);
    cudaMemsetAsync(flagaddr, 0, 2 * GRID * sizeof(int));

    cde_kernel<<<GRID, NTHR, SMEM>>>(coeffs, x_last, Wi, bi, W1, b1, W2, b2,
                                     W3, b3, Wr, br, out);
}

// round 12
// speedup vs baseline: 1.5396x; 1.5396x over previous
#include <cuda_runtime.h>
#include <math.h>

// Problem constants
#define BN     256
#define HN     128
#define CN     32
#define OUTN   32
#define NSTAGE 256   // 64 steps * 4 RK stages
#define GRID   128
#define NTHR   512

// ---------------- device global scratch (allocation-free) ----------------
__device__ float g_k[4][BN * HN];      // k1..k4 of current step
__device__ float g_Bv[BN * HN];        // h2 for current stage
__device__ float g_dX[BN * CN];        // dX/dt at current stage time
__device__ unsigned long long g_bar;   // grid barrier counter

struct SmemLayout {
    float W3s[128][256];     // 128 KB : this CTA's 8-h slice of W3 [i][hl*32+c]
    float W1s[128][128];     // 64 KB
    float BvT[128][36];      // transposed h2 tile [i][b], 144B row stride (16B aligned)
    float dXs[32][36];
    float ys[2][128];
    float As[2][128];
    float P[2][2][128];      // phase-1 partial sums [half][bb][j]
    float z0s[2][128];
    float b1s[128];
    float b2s[128];
};

__device__ __forceinline__ float softplus_f(float x) {
    return fmaxf(x, 0.0f) + log1pf(__expf(-fabsf(x)));
}
__device__ __forceinline__ float tanh_fast(float x) {
    float e = __expf(2.0f * x);
    return 1.0f - __fdividef(2.0f, e + 1.0f);
}
__device__ __forceinline__ unsigned long long pk2(float lo, float hi) {
    unsigned long long r;
    asm("mov.b64 %0, {%1,%2};" : "=l"(r) : "f"(lo), "f"(hi));
    return r;
}
__device__ __forceinline__ void unpk2(unsigned long long v, float& lo, float& hi) {
    asm("mov.b64 {%0,%1}, %2;" : "=f"(lo), "=f"(hi) : "l"(v));
}
__device__ __forceinline__ void ffma2(unsigned long long& d, unsigned long long a,
                                      unsigned long long b) {
    asm("fma.rn.f32x2 %0, %1, %2, %0;" : "+l"(d) : "l"(a), "l"(b));
}

__device__ __forceinline__ void grid_barrier(unsigned long long tgt) {
    __syncthreads();
    if (threadIdx.x == 0) {
        __threadfence();
        atomicAdd(&g_bar, 1ULL);
        while (*(volatile unsigned long long*)&g_bar < tgt) { }
    }
    __syncthreads();
}

__global__ __launch_bounds__(NTHR, 1) void cde_kernel(
    const float* __restrict__ coeffs, const float* __restrict__ x_last,
    const float* __restrict__ Wi,     const float* __restrict__ bi,
    const float* __restrict__ W1,     const float* __restrict__ b1,
    const float* __restrict__ W2,     const float* __restrict__ b2,
    const float* __restrict__ W3,     const float* __restrict__ b3,
    const float* __restrict__ Wr,     const float* __restrict__ br,
    float* __restrict__ out)
{
    extern __shared__ char smraw[];
    SmemLayout& sm = *reinterpret_cast<SmemLayout*>(smraw);

    const int tid = threadIdx.x;
    const int ci  = blockIdx.x;
    const int hg  = ci & 15;          // h-group: h in [hg*8, hg*8+8)
    const int bB  = (ci >> 4) * 32;   // phase-2 b-tile base

    // ---- one-time smem loads ----
    for (int t = tid; t < 128 * 256; t += NTHR) {
        int i = t >> 8, cc = t & 255;
        sm.W3s[i][cc] = W3[i * 4096 + hg * 256 + cc];
    }
    for (int t = tid; t < 128 * 128; t += NTHR)
        sm.W1s[t >> 7][t & 127] = W1[t];
    if (tid < 128) { sm.b1s[tid] = b1[tid]; sm.b2s[tid] = b2[tid]; }

    // ---- phase-2 mapping (first 256 threads = 8 warps) ----
    const int wid  = tid >> 5;
    const int lane = tid & 31;
    const int b0   = (wid & 3) * 8;          // 8 b-rows per warp (broadcast operand)
    const int cch  = wid >> 2;               // cc-half (0/1), valid for wid<8
    const int hl   = (cch & 1) * 4 + (lane >> 3);  // local h 0..7
    const int c0   = (lane & 7) * 4;
    const int h    = hg * 8 + hl;

    float b3v[4];
    #pragma unroll
    for (int u = 0; u < 4; u++) b3v[u] = b3[h * 32 + c0 + u];

    // ---- phase-1 mapping ----
    const int half = tid >> 8;        // i-half (0/1)
    const int rem  = tid & 255;
    const int bb   = rem >> 7;        // batch row within CTA (0/1)
    const int j    = rem & 127;
    const int bme  = ci * 2 + bb;

    __syncthreads();

    for (int s = 0; s < NSTAGE; s++) {
        const int s4 = s & 3;
        const int n  = s >> 2;

        // ============ phase 1 : y, dX, h1, h2  (2 batch rows / CTA) ============
        if (half == 0) {
            float y;
            if (s == 0) {
                float acc = bi[j];
                const float* cb = coeffs + bme * 8192;
                #pragma unroll
                for (int c = 0; c < CN; c++) acc = fmaf(cb[c], Wi[c * 128 + j], acc);
                sm.z0s[bb][j] = acc;
                y = acc;
            } else {
                float z0 = sm.z0s[bb][j];
                if (s4 == 0) {
                    float k1 = __ldcg(&g_k[0][bme * 128 + j]);
                    float k2 = __ldcg(&g_k[1][bme * 128 + j]);
                    float k3 = __ldcg(&g_k[2][bme * 128 + j]);
                    float k4 = __ldcg(&g_k[3][bme * 128 + j]);
                    z0 += (k1 + 3.0f * (k2 + k3) + k4) * 0.125f;
                    sm.z0s[bb][j] = z0;
                    y = z0;
                } else if (s4 == 1) {
                    y = z0 + __ldcg(&g_k[0][bme * 128 + j]) * (1.0f / 3.0f);
                } else if (s4 == 2) {
                    y = z0 + __ldcg(&g_k[1][bme * 128 + j])
                           - __ldcg(&g_k[0][bme * 128 + j]) * (1.0f / 3.0f);
                } else {
                    y = z0 + __ldcg(&g_k[0][bme * 128 + j])
                           - __ldcg(&g_k[1][bme * 128 + j])
                           + __ldcg(&g_k[2][bme * 128 + j]);
                }
            }
            sm.ys[bb][j] = y;

            if (j < CN) {
                float t;
                if      (s4 == 0) t = (float)n;
                else if (s4 == 1) t = (float)n + (1.0f / 3.0f);
                else if (s4 == 2) t = (float)n + (2.0f / 3.0f);
                else              t = (float)(n + 1);
                int   pid  = (int)floorf(t); if (pid > 63) pid = 63;
                float frac = t - (float)pid;
                const float* cb = coeffs + bme * 8192 + pid * 128;
                float dv = fmaf(fmaf(cb[96 + j], frac, cb[64 + j]), frac, cb[32 + j]);
                __stcg(&g_dX[bme * 32 + j], dv);
            }
        }
        __syncthreads();

        {   // matvec1 (i-split over halves, 2 accumulators)
            const int i0 = half * 64;
            float a0 = 0.0f, a1 = 0.0f;
            #pragma unroll 8
            for (int i = 0; i < 64; i += 2) {
                a0 = fmaf(sm.ys[bb][i0 + i],     sm.W1s[i0 + i][j],     a0);
                a1 = fmaf(sm.ys[bb][i0 + i + 1], sm.W1s[i0 + i + 1][j], a1);
            }
            sm.P[half][bb][j] = a0 + a1;
        }
        __syncthreads();
        if (half == 0)
            sm.As[bb][j] = softplus_f(sm.P[0][bb][j] + sm.P[1][bb][j] + sm.b1s[j]);
        __syncthreads();
        {   // matvec2
            const int i0 = half * 64;
            float a0 = 0.0f, a1 = 0.0f;
            #pragma unroll 8
            for (int i = 0; i < 64; i += 2) {
                a0 = fmaf(sm.As[bb][i0 + i],     __ldg(&W2[(i0 + i) * 128 + j]),     a0);
                a1 = fmaf(sm.As[bb][i0 + i + 1], __ldg(&W2[(i0 + i + 1) * 128 + j]), a1);
            }
            sm.P[half][bb][j] = a0 + a1;
        }
        __syncthreads();
        if (half == 0)
            __stcg(&g_Bv[bme * 128 + j],
                   softplus_f(sm.P[0][bb][j] + sm.P[1][bb][j] + sm.b2s[j]));

        grid_barrier((unsigned long long)(2 * s + 1) * GRID);

        // ============ phase 2 : k = tanh(h2 @ W3 + b3) . dX ============
        // stage Bv transposed + dX (all 512 threads)
        for (int t = tid; t < 32 * 128; t += NTHR) {
            int r = t >> 7, q = t & 127;
            sm.BvT[q][r] = __ldcg(&g_Bv[(bB + r) * 128 + q]);
        }
        for (int t = tid; t < 32 * 32; t += NTHR) {
            int r = t >> 5, q = t & 31;
            sm.dXs[r][q] = __ldcg(&g_dX[(bB + r) * 32 + q]);
        }
        __syncthreads();

        if (tid < 256) {
            // 8b x 4cc per thread; Bv operand is warp-uniform (smem broadcast)
            unsigned long long acc[4][4];
            #pragma unroll
            for (int p = 0; p < 4; p++)
                #pragma unroll
                for (int u = 0; u < 4; u++) acc[p][u] = 0ULL;

            #pragma unroll 4
            for (int i = 0; i < 128; i++) {
                float4 w4 = *reinterpret_cast<const float4*>(&sm.W3s[i][hl * 32 + c0]);
                ulonglong2 bva = *reinterpret_cast<const ulonglong2*>(&sm.BvT[i][b0]);
                ulonglong2 bvb = *reinterpret_cast<const ulonglong2*>(&sm.BvT[i][b0 + 4]);
                unsigned long long w0  = pk2(w4.x, w4.x);
                unsigned long long w1d = pk2(w4.y, w4.y);
                unsigned long long w2d = pk2(w4.z, w4.z);
                unsigned long long w3d = pk2(w4.w, w4.w);
                ffma2(acc[0][0], bva.x, w0);
                ffma2(acc[0][1], bva.x, w1d);
                ffma2(acc[0][2], bva.x, w2d);
                ffma2(acc[0][3], bva.x, w3d);
                ffma2(acc[1][0], bva.y, w0);
                ffma2(acc[1][1], bva.y, w1d);
                ffma2(acc[1][2], bva.y, w2d);
                ffma2(acc[1][3], bva.y, w3d);
                ffma2(acc[2][0], bvb.x, w0);
                ffma2(acc[2][1], bvb.x, w1d);
                ffma2(acc[2][2], bvb.x, w2d);
                ffma2(acc[2][3], bvb.x, w3d);
                ffma2(acc[3][0], bvb.y, w0);
                ffma2(acc[3][1], bvb.y, w1d);
                ffma2(acc[3][2], bvb.y, w2d);
                ffma2(acc[3][3], bvb.y, w3d);
            }

            float pj[8];
            #pragma unroll
            for (int p = 0; p < 4; p++) {
                float s0 = 0.0f, s1 = 0.0f;
                #pragma unroll
                for (int u = 0; u < 4; u++) {
                    float lo, hi;
                    unpk2(acc[p][u], lo, hi);
                    s0 = fmaf(tanh_fast(lo + b3v[u]), sm.dXs[b0 + 2 * p][c0 + u], s0);
                    s1 = fmaf(tanh_fast(hi + b3v[u]), sm.dXs[b0 + 2 * p + 1][c0 + u], s1);
                }
                pj[2 * p] = s0; pj[2 * p + 1] = s1;
            }
            // reduce over the 8-lane c-groups (lanes sharing hl)
            #pragma unroll
            for (int m = 1; m < 8; m <<= 1)
                #pragma unroll
                for (int r = 0; r < 8; r++)
                    pj[r] += __shfl_xor_sync(0xffffffffu, pj[r], m);

            if ((lane & 7) == 0) {
                #pragma unroll
                for (int r = 0; r < 8; r++)
                    __stcg(&g_k[s4][(bB + b0 + r) * 128 + h], pj[r]);
            }
        }

        grid_barrier((unsigned long long)(2 * s + 2) * GRID);
    }

    // ================= epilogue: fold last step, readout =================
    if (half == 0) {
        float z0 = sm.z0s[bb][j];
        float k1 = __ldcg(&g_k[0][bme * 128 + j]);
        float k2 = __ldcg(&g_k[1][bme * 128 + j]);
        float k3 = __ldcg(&g_k[2][bme * 128 + j]);
        float k4 = __ldcg(&g_k[3][bme * 128 + j]);
        sm.ys[bb][j] = z0 + (k1 + 3.0f * (k2 + k3) + k4) * 0.125f;
    }
    __syncthreads();
    if (half == 0 && j < OUTN) {
        float acc = br[j] + x_last[bme * OUTN + j];
        #pragma unroll 8
        for (int hh = 0; hh < 128; hh++)
            acc = fmaf(sm.ys[bb][hh], Wr[hh * OUTN + j], acc);
        out[bme * OUTN + j] = acc;
    }
}

extern "C" void kernel_launch(void* const* d_in, const int* in_sizes, int n_in,
                              void* d_out, int out_size) {
    const float* coeffs = (const float*)d_in[0];
    const float* x_last = (const float*)d_in[1];
    const float* Wi     = (const float*)d_in[2];
    const float* bi     = (const float*)d_in[3];
    const float* W1     = (const float*)d_in[4];
    const float* b1     = (const float*)d_in[5];
    const float* W2     = (const float*)d_in[6];
    const float* b2     = (const float*)d_in[7];
    const float* W3     = (const float*)d_in[8];
    const float* b3     = (const float*)d_in[9];
    const float* Wr     = (const float*)d_in[10];
    const float* br     = (const float*)d_in[11];
    float* out = (float*)d_out;

    static const size_t SMEM = sizeof(SmemLayout);
    cudaFuncSetAttribute(cde_kernel, cudaFuncAttributeMaxDynamicSharedMemorySize, (int)SMEM);

    void* baraddr = nullptr;
    cudaGetSymbolAddress(&baraddr, g_bar);
    cudaMemsetAsync(baraddr, 0, sizeof(unsigned long long));

    cde_kernel<<<GRID, NTHR, SMEM>>>(coeffs, x_last, Wi, bi, W1, b1, W2, b2,
                                     W3, b3, Wr, br, out);
}